// round 5
// baseline (speedup 1.0000x reference)
#include <cuda_runtime.h>
#include <cstdint>

#define NLAYERS 2
#define NMAT 4
#define NE 9
#define D 128
#define NTOK 65536
#define TILE_M 128
#define NBLK (NTOK / TILE_M + NE)     // 521
#define INVALID 0xFFFFFFFFu
#define NTHR 512

#define PADX 132                       // Xs row stride (floats)
#define PADW 36                        // W slab row stride (floats)
#define SLAB_FLOATS (NMAT * D * PADW)  // 18432 floats = 73728 B per buffer

#define OFF_TOK  0
#define OFF_BIAS 512
#define OFF_X    2560
#define OFF_W    (OFF_X + TILE_M * PADX * 4)          // 70144
#define SMEM_TOTAL (OFF_W + 2 * SLAB_FLOATS * 4)      // 217600 B

// ---------------- device scratch ----------------
__device__ unsigned g_counts[NE];
__device__ unsigned g_cursor[NE];
__device__ unsigned g_off[NE];
__device__ unsigned g_list[NBLK * TILE_M];
__device__ float g_Wt[NLAYERS * NMAT * NE * D * D];   // tf32-rounded weights

// ---------------- helpers ----------------
__device__ __forceinline__ float to_tf32(float x) {
    uint32_t u; asm("cvt.rna.tf32.f32 %0, %1;" : "=r"(u) : "f"(x));
    return __uint_as_float(u);
}
__device__ __forceinline__ float ex2a(float x) {
    float r; asm("ex2.approx.f32 %0, %1;" : "=f"(r) : "f"(x)); return r;
}
__device__ __forceinline__ float rcpa(float x) {
    float r; asm("rcp.approx.f32 %0, %1;" : "=f"(r) : "f"(x)); return r;
}
__device__ __forceinline__ float sigm(float v) {
    return rcpa(1.0f + ex2a(-1.4426950408889634f * v));
}
__device__ __forceinline__ float tanh_(float v) {
    return fmaf(2.0f, rcpa(1.0f + ex2a(-2.8853900817779268f * v)), -1.0f);
}
__device__ __forceinline__ void mma8(float* d, const uint32_t* a, uint32_t b0, uint32_t b1) {
    asm volatile(
        "mma.sync.aligned.m16n8k8.row.col.f32.tf32.tf32.f32 "
        "{%0,%1,%2,%3}, {%4,%5,%6,%7}, {%8,%9}, {%0,%1,%2,%3};"
        : "+f"(d[0]), "+f"(d[1]), "+f"(d[2]), "+f"(d[3])
        : "r"(a[0]), "r"(a[1]), "r"(a[2]), "r"(a[3]), "r"(b0), "r"(b1));
}
__device__ __forceinline__ void cpa16(uint32_t dst, const float* src) {
    asm volatile("cp.async.cg.shared.global [%0], [%1], 16;"
                 :: "r"(dst), "l"(__cvta_generic_to_global(src)) : "memory");
}

// ---------------- prep kernels ----------------
__global__ void prep_zero() {
    int stride = gridDim.x * blockDim.x;
    for (int i = blockIdx.x * blockDim.x + threadIdx.x; i < NBLK * TILE_M; i += stride)
        g_list[i] = INVALID;
    if (blockIdx.x == 0 && threadIdx.x < NE) {
        g_counts[threadIdx.x] = 0;
        g_cursor[threadIdx.x] = 0;
    }
}
__global__ void prep_hist(const int* __restrict__ pos) {
    __shared__ unsigned h[NE];
    if (threadIdx.x < NE) h[threadIdx.x] = 0;
    __syncthreads();
    int t = blockIdx.x * blockDim.x + threadIdx.x;
    int e = min(pos[t], NE - 1);
    atomicAdd(&h[e], 1u);
    __syncthreads();
    if (threadIdx.x < NE) atomicAdd(&g_counts[threadIdx.x], h[threadIdx.x]);
}
__global__ void prep_off() {
    unsigned o = 0;
    for (int e = 0; e < NE; e++) {
        g_off[e] = o;
        o += ((g_counts[e] + TILE_M - 1) / TILE_M) * TILE_M;
    }
}
__global__ void prep_scatter(const int* __restrict__ pos) {
    __shared__ unsigned sc[NE];
    __shared__ unsigned sb[NE];
    if (threadIdx.x < NE) sc[threadIdx.x] = 0;
    __syncthreads();
    int t = blockIdx.x * blockDim.x + threadIdx.x;
    int e = min(pos[t], NE - 1);
    unsigned my = atomicAdd(&sc[e], 1u);
    __syncthreads();
    if (threadIdx.x < NE) sb[threadIdx.x] = atomicAdd(&g_cursor[threadIdx.x], sc[threadIdx.x]);
    __syncthreads();
    g_list[g_off[e] + sb[e] + my] = (unsigned)t;
}
__global__ void prep_round(const float* __restrict__ W) {
    int i = blockIdx.x * blockDim.x + threadIdx.x;
    g_Wt[i] = to_tf32(W[i]);
}

// ---------------- main kernel ----------------
__global__ __launch_bounds__(NTHR, 1) void mpt_main(
    const int* __restrict__ pos,
    const float* __restrict__ X0,
    const float* __restrict__ Bv,
    float* __restrict__ Out)
{
    extern __shared__ __align__(16) char sm[];
    unsigned* s_tok = (unsigned*)(sm + OFF_TOK);
    float* Bs = (float*)(sm + OFF_BIAS);
    float* Xs = (float*)(sm + OFF_X);
    float* Ws = (float*)(sm + OFF_W);
    const uint32_t smW = (uint32_t)__cvta_generic_to_shared(sm + OFF_W);
    const int tid = threadIdx.x;

    if (tid < TILE_M) s_tok[tid] = g_list[blockIdx.x * TILE_M + tid];
    __syncthreads();
    const unsigned tok0 = s_tok[0];
    if (tok0 == INVALID) return;
    const int e = min(pos[tok0], NE - 1);

    // prologue: prefetch (l=0, cg=0) into buffer 0
    {
        #pragma unroll
        for (int i = 0; i < 8; i++) {
            int idx = tid + i * NTHR;
            int m = idx >> 10, rem = idx & 1023, k = rem >> 3, c8 = rem & 7;
            const float* src = g_Wt + ((size_t)m * NE + e) * (D * D) + k * D + c8 * 4;
            cpa16(smW + m * (D * PADW * 4) + k * (PADW * 4) + c8 * 16, src);
        }
        asm volatile("cp.async.commit_group;" ::: "memory");
    }

    // gather X tile (tf32-rounded) into padded SMEM
    for (int i = tid; i < TILE_M * 32; i += NTHR) {
        int r = i >> 5, c = i & 31;
        unsigned t = s_tok[r];
        if (t == INVALID) t = tok0;
        float4 v = reinterpret_cast<const float4*>(X0 + (size_t)t * D)[c];
        v.x = to_tf32(v.x); v.y = to_tf32(v.y); v.z = to_tf32(v.z); v.w = to_tf32(v.w);
        *reinterpret_cast<float4*>(Xs + (size_t)r * PADX + c * 4) = v;
    }

    const int lane = tid & 31, w = tid >> 5;
    const int wid7 = w & 7;            // row strip 0..7
    const int half = w >> 3;           // nt half: 0 -> nt{0,1}, 1 -> nt{2,3}
    const int lk = lane & 3, ln = lane >> 2;
    const int row0 = wid7 * 16 + ln;

    float nxs[4][8];
    int buf = 0;

    #pragma unroll 1
    for (int l = 0; l < NLAYERS; l++) {
        for (int i = tid; i < NMAT * D; i += NTHR)
            Bs[i] = Bv[((size_t)(l * NMAT + (i >> 7)) * NE + e) * D + (i & 127)];

        #pragma unroll
        for (int cg = 0; cg < 4; cg++) {
            asm volatile("cp.async.wait_group 0;" ::: "memory");
            __syncthreads();
            int g = l * 4 + cg;
            if (g < 7) {
                int nl = (g + 1) >> 2, ncg = (g + 1) & 3;
                uint32_t dbase = smW + (buf ^ 1) * (SLAB_FLOATS * 4);
                #pragma unroll
                for (int i = 0; i < 8; i++) {
                    int idx = tid + i * NTHR;
                    int m = idx >> 10, rem = idx & 1023, k = rem >> 3, c8 = rem & 7;
                    const float* src = g_Wt + ((size_t)(nl * NMAT + m) * NE + e) * (D * D)
                                       + k * D + ncg * 32 + c8 * 4;
                    cpa16(dbase + m * (D * PADW * 4) + k * (PADW * 4) + c8 * 16, src);
                }
                asm volatile("cp.async.commit_group;" ::: "memory");
            }

            // ---- GEMM: warp covers rows [wid7*16,+16), cols nt {half*2, half*2+1}, 4 mats
            float acc[4][2][4];
            #pragma unroll
            for (int m = 0; m < 4; m++)
                #pragma unroll
                for (int nt = 0; nt < 2; nt++)
                    #pragma unroll
                    for (int c = 0; c < 4; c++) acc[m][nt][c] = 0.0f;

            const uint32_t* xa0 = (const uint32_t*)(Xs + row0 * PADX + lk);
            const uint32_t* xa1 = xa0 + 8 * PADX;
            const uint32_t* bb  = (const uint32_t*)(Ws + buf * SLAB_FLOATS
                                                    + lk * PADW + half * 16 + ln);

            #pragma unroll 4
            for (int ks = 0; ks < 16; ks++) {
                uint32_t a[4];
                a[0] = xa0[ks * 8];
                a[1] = xa1[ks * 8];
                a[2] = xa0[ks * 8 + 4];
                a[3] = xa1[ks * 8 + 4];
                const uint32_t* bk = bb + ks * 8 * PADW;
                #pragma unroll
                for (int m = 0; m < 4; m++) {
                    const uint32_t* bm = bk + m * D * PADW;
                    #pragma unroll
                    for (int nt = 0; nt < 2; nt++) {
                        uint32_t b0 = bm[nt * 8];
                        uint32_t b1 = bm[nt * 8 + 4 * PADW];
                        mma8(acc[m][nt], a, b0, b1);
                    }
                }
            }

            // ---- gating, stash in registers ----
            #pragma unroll
            for (int nt = 0; nt < 2; nt++) {
                int ntg = half * 2 + nt;
                #pragma unroll
                for (int h = 0; h < 2; h++) {
                    int col = cg * 32 + ntg * 8 + lk * 2;
                    const float* xr = Xs + (row0 + h * 8) * PADX + col;
                    #pragma unroll
                    for (int c = 0; c < 2; c++) {
                        float sf = acc[0][nt][h * 2 + c] + Bs[0 * D + col + c];
                        float lg = acc[1][nt][h * 2 + c] + Bs[1 * D + col + c];
                        float lf = acc[2][nt][h * 2 + c] + Bs[2 * D + col + c];
                        float of = acc[3][nt][h * 2 + c] + Bs[3 * D + col + c];
                        float xv = xr[c];
                        float nr = xv * sigm(sf) + tanh_(lg) * sigm(lf);
                        nxs[cg][nt * 4 + h * 2 + c] = tanh_(nr) * sigm(of);
                    }
                }
            }
            buf ^= 1;
        }

        __syncthreads();   // all GEMM/gating reads of old Xs complete
        #pragma unroll
        for (int cg = 0; cg < 4; cg++) {
            #pragma unroll
            for (int nt = 0; nt < 2; nt++) {
                int ntg = half * 2 + nt;
                #pragma unroll
                for (int h = 0; h < 2; h++) {
                    float v0 = nxs[cg][nt * 4 + h * 2 + 0];
                    float v1 = nxs[cg][nt * 4 + h * 2 + 1];
                    if (l == 0) { v0 = to_tf32(v0); v1 = to_tf32(v1); }
                    *reinterpret_cast<float2*>(Xs + (row0 + h * 8) * PADX
                                               + cg * 32 + ntg * 8 + lk * 2) =
                        make_float2(v0, v1);
                }
            }
        }
        __syncthreads();
    }

    // coalesced store of final X
    for (int i = tid; i < TILE_M * 32; i += NTHR) {
        int r = i >> 5, c = i & 31;
        unsigned t = s_tok[r];
        if (t != INVALID) {
            float4 v = *reinterpret_cast<const float4*>(Xs + (size_t)r * PADX + c * 4);
            reinterpret_cast<float4*>(Out + (size_t)t * D)[c] = v;
        }
    }
}

// ---------------- launch ----------------
extern "C" void kernel_launch(void* const* d_in, const int* in_sizes, int n_in,
                              void* d_out, int out_size)
{
    const int*   pos = (const int*)d_in[0];
    const float* X0  = (const float*)d_in[1];
    const float* W   = (const float*)d_in[2];
    const float* Bv  = (const float*)d_in[3];
    float*       Out = (float*)d_out;
    (void)in_sizes; (void)n_in; (void)out_size;

    cudaFuncSetAttribute(mpt_main, cudaFuncAttributeMaxDynamicSharedMemorySize, SMEM_TOTAL);

    prep_zero<<<64, 256>>>();
    prep_hist<<<NTOK / 256, 256>>>(pos);
    prep_off<<<1, 1>>>();
    prep_scatter<<<NTOK / 256, 256>>>(pos);
    prep_round<<<(NLAYERS * NMAT * NE * D * D) / 256, 256>>>(W);
    mpt_main<<<NBLK, NTHR, SMEM_TOTAL>>>(pos, X0, Bv, Out);
}

// round 6
// speedup vs baseline: 2.1184x; 2.1184x over previous
#include <cuda_runtime.h>
#include <cstdint>

#define NLAYERS 2
#define NMAT 4
#define NE 9
#define D 128
#define NTOK 65536
#define TILE_M 128
#define NBLK (NTOK / TILE_M + NE)     // 521
#define INVALID 0xFFFFFFFFu
#define NTHR 256

#define PADX 132                       // Xs row stride (floats)
#define SLAB_FLOATS (NMAT * 16 * 256)  // 16384 floats = 65536 B per slab (one cg)

#define OFF_TOK  0
#define OFF_BIAS 512
#define OFF_X    2560
#define OFF_W    (OFF_X + TILE_M * PADX * 4)          // 70144
#define SMEM_TOTAL (OFF_W + 2 * SLAB_FLOATS * 4)      // 201216 B

// ---------------- device scratch ----------------
__device__ unsigned g_counts[NE];
__device__ unsigned g_cursor[NE];
__device__ unsigned g_off[NE];
__device__ unsigned g_list[NBLK * TILE_M];
// fragment-packed tf32 weights: [l][e][cg][j][ks][group(2)][lane(32)] float4
__device__ float4 g_Wp[NLAYERS * NE * 4 * NMAT * 16 * 64];

// ---------------- helpers ----------------
__device__ __forceinline__ float to_tf32(float x) {
    uint32_t u; asm("cvt.rna.tf32.f32 %0, %1;" : "=r"(u) : "f"(x));
    return __uint_as_float(u);
}
__device__ __forceinline__ float ex2a(float x) {
    float r; asm("ex2.approx.f32 %0, %1;" : "=f"(r) : "f"(x)); return r;
}
__device__ __forceinline__ float rcpa(float x) {
    float r; asm("rcp.approx.f32 %0, %1;" : "=f"(r) : "f"(x)); return r;
}
__device__ __forceinline__ float sigm(float v) {
    return rcpa(1.0f + ex2a(-1.4426950408889634f * v));
}
__device__ __forceinline__ float tanh_(float v) {
    return fmaf(2.0f, rcpa(1.0f + ex2a(-2.8853900817779268f * v)), -1.0f);
}
__device__ __forceinline__ void mma8(float* d, const uint32_t* a, float b0f, float b1f) {
    uint32_t b0 = __float_as_uint(b0f), b1 = __float_as_uint(b1f);
    asm volatile(
        "mma.sync.aligned.m16n8k8.row.col.f32.tf32.tf32.f32 "
        "{%0,%1,%2,%3}, {%4,%5,%6,%7}, {%8,%9}, {%0,%1,%2,%3};"
        : "+f"(d[0]), "+f"(d[1]), "+f"(d[2]), "+f"(d[3])
        : "r"(a[0]), "r"(a[1]), "r"(a[2]), "r"(a[3]), "r"(b0), "r"(b1));
}
__device__ __forceinline__ void cpa16(uint32_t dst, const void* src) {
    asm volatile("cp.async.cg.shared.global [%0], [%1], 16;"
                 :: "r"(dst), "l"(__cvta_generic_to_global(src)) : "memory");
}

// ---------------- prep kernels ----------------
__global__ void prep_zero() {
    int stride = gridDim.x * blockDim.x;
    for (int i = blockIdx.x * blockDim.x + threadIdx.x; i < NBLK * TILE_M; i += stride)
        g_list[i] = INVALID;
    if (blockIdx.x == 0 && threadIdx.x < NE) {
        g_counts[threadIdx.x] = 0;
        g_cursor[threadIdx.x] = 0;
    }
}
__global__ void prep_hist(const int* __restrict__ pos) {
    __shared__ unsigned h[NE];
    if (threadIdx.x < NE) h[threadIdx.x] = 0;
    __syncthreads();
    int t = blockIdx.x * blockDim.x + threadIdx.x;
    int e = min(pos[t], NE - 1);
    atomicAdd(&h[e], 1u);
    __syncthreads();
    if (threadIdx.x < NE) atomicAdd(&g_counts[threadIdx.x], h[threadIdx.x]);
}
__global__ void prep_off() {
    unsigned o = 0;
    for (int e = 0; e < NE; e++) {
        g_off[e] = o;
        o += ((g_counts[e] + TILE_M - 1) / TILE_M) * TILE_M;
    }
}
__global__ void prep_scatter(const int* __restrict__ pos) {
    __shared__ unsigned sc[NE];
    __shared__ unsigned sb[NE];
    if (threadIdx.x < NE) sc[threadIdx.x] = 0;
    __syncthreads();
    int t = blockIdx.x * blockDim.x + threadIdx.x;
    int e = min(pos[t], NE - 1);
    unsigned my = atomicAdd(&sc[e], 1u);
    __syncthreads();
    if (threadIdx.x < NE) sb[threadIdx.x] = atomicAdd(&g_cursor[threadIdx.x], sc[threadIdx.x]);
    __syncthreads();
    g_list[g_off[e] + sb[e] + my] = (unsigned)t;
}
// pack W[l,j,e][k][n] -> g_Wp fragment order, tf32-rounded
__global__ void prep_pack(const float* __restrict__ W) {
    int i = blockIdx.x * blockDim.x + threadIdx.x;   // 294912 threads
    int lane = i & 31;
    int g    = (i >> 5) & 1;
    int ks   = (i >> 6) & 15;
    int j    = (i >> 10) & 3;
    int cg   = (i >> 12) & 3;
    int i2   = i >> 14;
    int e    = i2 % NE;
    int l    = i2 / NE;
    int lk = lane & 3, ln = lane >> 2;
    const float* src = W + ((size_t)(l * NMAT + j) * NE + e) * (D * D);
    int ca = cg * 32 + (g * 2) * 8 + ln;
    int cb = ca + 8;
    float4 v;
    v.x = to_tf32(src[(8 * ks + lk) * D + ca]);
    v.y = to_tf32(src[(8 * ks + lk + 4) * D + ca]);
    v.z = to_tf32(src[(8 * ks + lk) * D + cb]);
    v.w = to_tf32(src[(8 * ks + lk + 4) * D + cb]);
    g_Wp[i] = v;
}

// ---------------- main kernel ----------------
__global__ __launch_bounds__(NTHR, 1) void mpt_main(
    const int* __restrict__ pos,
    const float* __restrict__ X0,
    const float* __restrict__ Bv,
    float* __restrict__ Out)
{
    extern __shared__ __align__(16) char sm[];
    unsigned* s_tok = (unsigned*)(sm + OFF_TOK);
    float* Bs = (float*)(sm + OFF_BIAS);
    float* Xs = (float*)(sm + OFF_X);
    const float4* Ws4 = (const float4*)(sm + OFF_W);
    const uint32_t smW = (uint32_t)__cvta_generic_to_shared(sm + OFF_W);
    const int tid = threadIdx.x;

    if (tid < TILE_M) s_tok[tid] = g_list[blockIdx.x * TILE_M + tid];
    __syncthreads();
    const unsigned tok0 = s_tok[0];
    if (tok0 == INVALID) return;
    const int e = min(pos[tok0], NE - 1);

    // prologue: prefetch (l=0, cg=0) slab into buffer 0 (contiguous 64 KB)
    {
        const float4* src = g_Wp + (size_t)e * 4 * (SLAB_FLOATS / 4);
        #pragma unroll
        for (int i = 0; i < 16; i++) {
            int idx = tid + i * NTHR;
            cpa16(smW + idx * 16, src + idx);
        }
        asm volatile("cp.async.commit_group;" ::: "memory");
    }

    // gather X tile (tf32-rounded) into padded SMEM
    for (int i = tid; i < TILE_M * 32; i += NTHR) {
        int r = i >> 5, c = i & 31;
        unsigned t = s_tok[r];
        if (t == INVALID) t = tok0;
        float4 v = reinterpret_cast<const float4*>(X0 + (size_t)t * D)[c];
        v.x = to_tf32(v.x); v.y = to_tf32(v.y); v.z = to_tf32(v.z); v.w = to_tf32(v.w);
        *reinterpret_cast<float4*>(Xs + (size_t)r * PADX + c * 4) = v;
    }

    const int lane = tid & 31, w = tid >> 5;
    const int lk = lane & 3, ln = lane >> 2;
    const int row0 = w * 16 + ln;

    float nxs[4][16];
    int buf = 0;

    #pragma unroll 1
    for (int l = 0; l < NLAYERS; l++) {
        for (int i = tid; i < NMAT * D; i += NTHR)
            Bs[i] = Bv[((size_t)(l * NMAT + (i >> 7)) * NE + e) * D + (i & 127)];

        #pragma unroll
        for (int cg = 0; cg < 4; cg++) {
            asm volatile("cp.async.wait_group 0;" ::: "memory");
            __syncthreads();   // slab ready; prev cg's reads of other buffer done
            int g = l * 4 + cg;
            if (g < 7) {
                int nl = (g + 1) >> 2, ncg = (g + 1) & 3;
                const float4* src = g_Wp + ((size_t)(nl * NE + e) * 4 + ncg) * (SLAB_FLOATS / 4);
                uint32_t dbase = smW + (buf ^ 1) * (SLAB_FLOATS * 4);
                #pragma unroll
                for (int i = 0; i < 16; i++) {
                    int idx = tid + i * NTHR;
                    cpa16(dbase + idx * 16, src + idx);
                }
                asm volatile("cp.async.commit_group;" ::: "memory");
            }

            // ---- GEMM: 128 rows x 32 cols x 128 k, 4 matrices ----
            float acc[4][4][4];
            #pragma unroll
            for (int m = 0; m < 4; m++)
                #pragma unroll
                for (int nt = 0; nt < 4; nt++)
                    #pragma unroll
                    for (int c = 0; c < 4; c++) acc[m][nt][c] = 0.0f;

            const uint32_t* xa0 = (const uint32_t*)(Xs + row0 * PADX + lk);
            const uint32_t* xa1 = xa0 + 8 * PADX;
            const float4* wb = Ws4 + buf * (SLAB_FLOATS / 4) + lane;

            #pragma unroll 2
            for (int ks = 0; ks < 16; ks++) {
                uint32_t a[4];
                a[0] = xa0[ks * 8];
                a[1] = xa1[ks * 8];
                a[2] = xa0[ks * 8 + 4];
                a[3] = xa1[ks * 8 + 4];
                #pragma unroll
                for (int m = 0; m < 4; m++) {
                    const float4* bm = wb + (m * 16 + ks) * 64;
                    float4 p0 = bm[0];
                    float4 p1 = bm[32];
                    mma8(acc[m][0], a, p0.x, p0.y);
                    mma8(acc[m][1], a, p0.z, p0.w);
                    mma8(acc[m][2], a, p1.x, p1.y);
                    mma8(acc[m][3], a, p1.z, p1.w);
                }
            }

            // ---- gating, stash in registers ----
            #pragma unroll
            for (int nt = 0; nt < 4; nt++) {
                #pragma unroll
                for (int h = 0; h < 2; h++) {
                    int col = cg * 32 + nt * 8 + lk * 2;
                    const float* xr = Xs + (row0 + h * 8) * PADX + col;
                    #pragma unroll
                    for (int c = 0; c < 2; c++) {
                        float sf = acc[0][nt][h * 2 + c] + Bs[0 * D + col + c];
                        float lg = acc[1][nt][h * 2 + c] + Bs[1 * D + col + c];
                        float lf = acc[2][nt][h * 2 + c] + Bs[2 * D + col + c];
                        float of = acc[3][nt][h * 2 + c] + Bs[3 * D + col + c];
                        float xv = xr[c];
                        float nr = xv * sigm(sf) + tanh_(lg) * sigm(lf);
                        nxs[cg][nt * 4 + h * 2 + c] = tanh_(nr) * sigm(of);
                    }
                }
            }
            buf ^= 1;
        }

        __syncthreads();   // all GEMM/gating reads of old Xs complete
        #pragma unroll
        for (int cg = 0; cg < 4; cg++) {
            #pragma unroll
            for (int nt = 0; nt < 4; nt++) {
                #pragma unroll
                for (int h = 0; h < 2; h++) {
                    float v0 = nxs[cg][nt * 4 + h * 2 + 0];
                    float v1 = nxs[cg][nt * 4 + h * 2 + 1];
                    if (l == 0) { v0 = to_tf32(v0); v1 = to_tf32(v1); }
                    *reinterpret_cast<float2*>(Xs + (row0 + h * 8) * PADX
                                               + cg * 32 + nt * 8 + lk * 2) =
                        make_float2(v0, v1);
                }
            }
        }
        __syncthreads();
    }

    // coalesced store of final X
    for (int i = tid; i < TILE_M * 32; i += NTHR) {
        int r = i >> 5, c = i & 31;
        unsigned t = s_tok[r];
        if (t != INVALID) {
            float4 v = *reinterpret_cast<const float4*>(Xs + (size_t)r * PADX + c * 4);
            reinterpret_cast<float4*>(Out + (size_t)t * D)[c] = v;
        }
    }
}

// ---------------- launch ----------------
extern "C" void kernel_launch(void* const* d_in, const int* in_sizes, int n_in,
                              void* d_out, int out_size)
{
    const int*   pos = (const int*)d_in[0];
    const float* X0  = (const float*)d_in[1];
    const float* W   = (const float*)d_in[2];
    const float* Bv  = (const float*)d_in[3];
    float*       Out = (float*)d_out;
    (void)in_sizes; (void)n_in; (void)out_size;

    cudaFuncSetAttribute(mpt_main, cudaFuncAttributeMaxDynamicSharedMemorySize, SMEM_TOTAL);

    prep_zero<<<64, 256>>>();
    prep_hist<<<NTOK / 256, 256>>>(pos);
    prep_off<<<1, 1>>>();
    prep_scatter<<<NTOK / 256, 256>>>(pos);
    prep_pack<<<(NLAYERS * NE * 4 * NMAT * 16 * 64) / 256, 256>>>(W);
    mpt_main<<<NBLK, NTHR, SMEM_TOTAL>>>(pos, X0, Bv, Out);
}

// round 7
// speedup vs baseline: 3.6230x; 1.7103x over previous
#include <cuda_runtime.h>
#include <cuda_fp16.h>
#include <cstdint>

#define NLAYERS 2
#define NMAT 4
#define NE 9
#define D 128
#define NTOK 65536
#define TILE_M 128
#define NBLK (NTOK / TILE_M + NE)     // 521
#define INVALID 0xFFFFFFFFu
#define NTHR 256

#define PADXH 136                      // Xs row stride in halves (272 B)
#define SLAB_U4 2048                   // uint4 per cg slab (32 KB)

#define OFF_TOK  0
#define OFF_BIAS 512
#define OFF_X    2560
#define OFF_W    (OFF_X + TILE_M * PADXH * 2)         // 37376
#define SMEM_TOTAL (OFF_W + 2 * SLAB_U4 * 16)         // 102912 B -> 2 CTAs/SM

// ---------------- device scratch ----------------
__device__ unsigned g_counts[NE];
__device__ unsigned g_cursor[NE];
__device__ unsigned g_off[NE];
__device__ unsigned g_list[NBLK * TILE_M];
// fragment-packed fp16 weights: [l][e][cg][j][ks][g2(2)][lane(32)] uint4
__device__ uint4 g_Wp[NLAYERS * NE * 4 * NMAT * 8 * 64];

// ---------------- helpers ----------------
__device__ __forceinline__ float ex2a(float x) {
    float r; asm("ex2.approx.f32 %0, %1;" : "=f"(r) : "f"(x)); return r;
}
__device__ __forceinline__ float rcpa(float x) {
    float r; asm("rcp.approx.f32 %0, %1;" : "=f"(r) : "f"(x)); return r;
}
__device__ __forceinline__ float sigm(float v) {
    return rcpa(1.0f + ex2a(-1.4426950408889634f * v));
}
__device__ __forceinline__ float tanh_(float v) {
    return fmaf(2.0f, rcpa(1.0f + ex2a(-2.8853900817779268f * v)), -1.0f);
}
__device__ __forceinline__ uint32_t pkh2(float lo, float hi) {
    __half2 h = __floats2half2_rn(lo, hi);
    return *reinterpret_cast<uint32_t*>(&h);
}
__device__ __forceinline__ float2 uph2(uint32_t u) {
    __half2 h = *reinterpret_cast<__half2*>(&u);
    return __half22float2(h);
}
__device__ __forceinline__ void mma16(float* d, const uint32_t* a, uint32_t b0, uint32_t b1) {
    asm volatile(
        "mma.sync.aligned.m16n8k16.row.col.f32.f16.f16.f32 "
        "{%0,%1,%2,%3}, {%4,%5,%6,%7}, {%8,%9}, {%0,%1,%2,%3};"
        : "+f"(d[0]), "+f"(d[1]), "+f"(d[2]), "+f"(d[3])
        : "r"(a[0]), "r"(a[1]), "r"(a[2]), "r"(a[3]), "r"(b0), "r"(b1));
}
__device__ __forceinline__ void cpa16(uint32_t dst, const void* src) {
    asm volatile("cp.async.cg.shared.global [%0], [%1], 16;"
                 :: "r"(dst), "l"(__cvta_generic_to_global(src)) : "memory");
}

// ---------------- prep kernels ----------------
__global__ void prep_zero() {
    int stride = gridDim.x * blockDim.x;
    for (int i = blockIdx.x * blockDim.x + threadIdx.x; i < NBLK * TILE_M; i += stride)
        g_list[i] = INVALID;
    if (blockIdx.x == 0 && threadIdx.x < NE) {
        g_counts[threadIdx.x] = 0;
        g_cursor[threadIdx.x] = 0;
    }
}
__global__ void prep_hist(const int* __restrict__ pos) {
    __shared__ unsigned h[NE];
    if (threadIdx.x < NE) h[threadIdx.x] = 0;
    __syncthreads();
    int t = blockIdx.x * blockDim.x + threadIdx.x;
    int e = min(pos[t], NE - 1);
    atomicAdd(&h[e], 1u);
    __syncthreads();
    if (threadIdx.x < NE) atomicAdd(&g_counts[threadIdx.x], h[threadIdx.x]);
}
__global__ void prep_off() {
    unsigned o = 0;
    for (int e = 0; e < NE; e++) {
        g_off[e] = o;
        o += ((g_counts[e] + TILE_M - 1) / TILE_M) * TILE_M;
    }
}
__global__ void prep_scatter(const int* __restrict__ pos) {
    __shared__ unsigned sc[NE];
    __shared__ unsigned sb[NE];
    if (threadIdx.x < NE) sc[threadIdx.x] = 0;
    __syncthreads();
    int t = blockIdx.x * blockDim.x + threadIdx.x;
    int e = min(pos[t], NE - 1);
    unsigned my = atomicAdd(&sc[e], 1u);
    __syncthreads();
    if (threadIdx.x < NE) sb[threadIdx.x] = atomicAdd(&g_cursor[threadIdx.x], sc[threadIdx.x]);
    __syncthreads();
    g_list[g_off[e] + sb[e] + my] = (unsigned)t;
}
// pack W[l,j,e][k][n] -> fp16 fragment order
__global__ void prep_pack(const float* __restrict__ W) {
    int i = blockIdx.x * blockDim.x + threadIdx.x;   // 147456 threads
    int lane = i & 31;
    int g2   = (i >> 5) & 1;
    int ks   = (i >> 6) & 7;
    int j    = (i >> 9) & 3;
    int cg   = (i >> 11) & 3;
    int i2   = i >> 13;
    int e    = i2 % NE;
    int l    = i2 / NE;
    int lk = lane & 3, ln = lane >> 2;
    const float* src = W + ((size_t)(l * NMAT + j) * NE + e) * (D * D);
    int k0 = ks * 16 + lk * 2;
    int colA = cg * 32 + (g2 * 2) * 8 + ln;
    int colB = colA + 8;
    uint4 v;
    v.x = pkh2(src[(k0    ) * D + colA], src[(k0 + 1) * D + colA]);
    v.y = pkh2(src[(k0 + 8) * D + colA], src[(k0 + 9) * D + colA]);
    v.z = pkh2(src[(k0    ) * D + colB], src[(k0 + 1) * D + colB]);
    v.w = pkh2(src[(k0 + 8) * D + colB], src[(k0 + 9) * D + colB]);
    g_Wp[i] = v;
}

// ---------------- main kernel ----------------
__global__ __launch_bounds__(NTHR, 2) void mpt_main(
    const int* __restrict__ pos,
    const float* __restrict__ X0,
    const float* __restrict__ Bv,
    float* __restrict__ Out)
{
    extern __shared__ __align__(16) char sm[];
    unsigned* s_tok = (unsigned*)(sm + OFF_TOK);
    float* Bs = (float*)(sm + OFF_BIAS);
    uint32_t* Xs = (uint32_t*)(sm + OFF_X);      // fp16x2, row stride 68 uint32
    const uint4* Ws4 = (const uint4*)(sm + OFF_W);
    const uint32_t smW = (uint32_t)__cvta_generic_to_shared(sm + OFF_W);
    const int tid = threadIdx.x;

    if (tid < TILE_M) s_tok[tid] = g_list[blockIdx.x * TILE_M + tid];
    __syncthreads();
    const unsigned tok0 = s_tok[0];
    if (tok0 == INVALID) return;
    const int e = min(pos[tok0], NE - 1);

    // prologue: prefetch (l=0, cg=0) slab into buffer 0 (contiguous 32 KB)
    {
        const uint4* src = g_Wp + (size_t)e * 4 * SLAB_U4;
        #pragma unroll
        for (int i = 0; i < 8; i++) {
            int idx = tid + i * NTHR;
            cpa16(smW + idx * 16, src + idx);
        }
        asm volatile("cp.async.commit_group;" ::: "memory");
    }

    // gather X tile -> fp16 SMEM
    for (int i = tid; i < TILE_M * 32; i += NTHR) {
        int r = i >> 5, c = i & 31;
        unsigned t = s_tok[r];
        if (t == INVALID) t = tok0;
        float4 v = reinterpret_cast<const float4*>(X0 + (size_t)t * D)[c];
        uint2 p = make_uint2(pkh2(v.x, v.y), pkh2(v.z, v.w));
        *reinterpret_cast<uint2*>(Xs + r * (PADXH / 2) + c * 2) = p;
    }

    const int lane = tid & 31, w = tid >> 5;
    const int lk = lane & 3, ln = lane >> 2;
    const int row0 = w * 16 + ln;

    uint32_t nxs[4][8];    // packed half2 gating results [cg][nt*2+h]
    int buf = 0;

    #pragma unroll 1
    for (int l = 0; l < NLAYERS; l++) {
        for (int i = tid; i < NMAT * D; i += NTHR)
            Bs[i] = Bv[((size_t)(l * NMAT + (i >> 7)) * NE + e) * D + (i & 127)];

        #pragma unroll
        for (int cg = 0; cg < 4; cg++) {
            asm volatile("cp.async.wait_group 0;" ::: "memory");
            __syncthreads();   // slab ready; prev cg's reads of other buffer done
            int g = l * 4 + cg;
            if (g < 7) {
                int nl = (g + 1) >> 2, ncg = (g + 1) & 3;
                const uint4* src = g_Wp + ((size_t)(nl * NE + e) * 4 + ncg) * SLAB_U4;
                uint32_t dbase = smW + (buf ^ 1) * (SLAB_U4 * 16);
                #pragma unroll
                for (int i = 0; i < 8; i++) {
                    int idx = tid + i * NTHR;
                    cpa16(dbase + idx * 16, src + idx);
                }
                asm volatile("cp.async.commit_group;" ::: "memory");
            }

            // ---- GEMM: 128 rows x 32 cols x 128 k, 4 matrices, fp16 ----
            float acc[4][4][4];
            #pragma unroll
            for (int m = 0; m < 4; m++)
                #pragma unroll
                for (int nt = 0; nt < 4; nt++)
                    #pragma unroll
                    for (int c = 0; c < 4; c++) acc[m][nt][c] = 0.0f;

            const uint32_t* xa0 = Xs + row0 * (PADXH / 2) + lk;
            const uint32_t* xa1 = xa0 + 8 * (PADXH / 2);
            const uint4* wb = Ws4 + buf * SLAB_U4 + lane;

            #pragma unroll 2
            for (int ks = 0; ks < 8; ks++) {
                uint32_t a[4];
                a[0] = xa0[ks * 8];
                a[1] = xa1[ks * 8];
                a[2] = xa0[ks * 8 + 4];
                a[3] = xa1[ks * 8 + 4];
                #pragma unroll
                for (int m = 0; m < 4; m++) {
                    const uint4* bm = wb + (m * 8 + ks) * 64;
                    uint4 p0 = bm[0];
                    uint4 p1 = bm[32];
                    mma16(acc[m][0], a, p0.x, p0.y);
                    mma16(acc[m][1], a, p0.z, p0.w);
                    mma16(acc[m][2], a, p1.x, p1.y);
                    mma16(acc[m][3], a, p1.z, p1.w);
                }
            }

            // ---- gating, stash packed half2 in registers ----
            #pragma unroll
            for (int nt = 0; nt < 4; nt++) {
                #pragma unroll
                for (int h = 0; h < 2; h++) {
                    int col = cg * 32 + nt * 8 + lk * 2;
                    float2 xv = uph2(Xs[(row0 + h * 8) * (PADXH / 2) + cg * 16 + nt * 4 + lk]);
                    float v[2];
                    #pragma unroll
                    for (int c = 0; c < 2; c++) {
                        float sf = acc[0][nt][h * 2 + c] + Bs[0 * D + col + c];
                        float lg = acc[1][nt][h * 2 + c] + Bs[1 * D + col + c];
                        float lf = acc[2][nt][h * 2 + c] + Bs[2 * D + col + c];
                        float of = acc[3][nt][h * 2 + c] + Bs[3 * D + col + c];
                        float x1 = (c == 0) ? xv.x : xv.y;
                        float nr = x1 * sigm(sf) + tanh_(lg) * sigm(lf);
                        v[c] = tanh_(nr) * sigm(of);
                    }
                    nxs[cg][nt * 2 + h] = pkh2(v[0], v[1]);
                }
            }
            buf ^= 1;
        }

        __syncthreads();   // all GEMM/gating reads of old Xs complete
        #pragma unroll
        for (int cg = 0; cg < 4; cg++)
            #pragma unroll
            for (int nt = 0; nt < 4; nt++)
                #pragma unroll
                for (int h = 0; h < 2; h++)
                    Xs[(row0 + h * 8) * (PADXH / 2) + cg * 16 + nt * 4 + lk] =
                        nxs[cg][nt * 2 + h];
        __syncthreads();
    }

    // coalesced store of final X (fp16 -> fp32)
    for (int i = tid; i < TILE_M * 32; i += NTHR) {
        int r = i >> 5, c = i & 31;
        unsigned t = s_tok[r];
        if (t != INVALID) {
            uint2 p = *reinterpret_cast<const uint2*>(Xs + r * (PADXH / 2) + c * 2);
            float2 lo = uph2(p.x), hi = uph2(p.y);
            reinterpret_cast<float4*>(Out + (size_t)t * D)[c] =
                make_float4(lo.x, lo.y, hi.x, hi.y);
        }
    }
}

// ---------------- launch ----------------
extern "C" void kernel_launch(void* const* d_in, const int* in_sizes, int n_in,
                              void* d_out, int out_size)
{
    const int*   pos = (const int*)d_in[0];
    const float* X0  = (const float*)d_in[1];
    const float* W   = (const float*)d_in[2];
    const float* Bv  = (const float*)d_in[3];
    float*       Out = (float*)d_out;
    (void)in_sizes; (void)n_in; (void)out_size;

    cudaFuncSetAttribute(mpt_main, cudaFuncAttributeMaxDynamicSharedMemorySize, SMEM_TOTAL);

    prep_zero<<<64, 256>>>();
    prep_hist<<<NTOK / 256, 256>>>(pos);
    prep_off<<<1, 1>>>();
    prep_scatter<<<NTOK / 256, 256>>>(pos);
    prep_pack<<<(NLAYERS * NE * 4 * NMAT * 8 * 64) / 256, 256>>>(W);
    mpt_main<<<NBLK, NTHR, SMEM_TOTAL>>>(pos, X0, Bv, Out);
}

// round 8
// speedup vs baseline: 3.9338x; 1.0858x over previous
#include <cuda_runtime.h>
#include <cuda_fp16.h>
#include <cstdint>

#define NLAYERS 2
#define NMAT 4
#define NE 9
#define D 128
#define NTOK 65536
#define TILE_M 128
#define NBLK (NTOK / TILE_M + NE)     // 521
#define NTHR 128

#define XSTRIDE 68                     // uint32 (half2) per X row
#define SLAB_U4 1024                   // uint4 per 16-col chunk slab (16 KB)

#define OFF_TOK  0
#define OFF_BIAS 1024
#define OFF_X0   3072
#define OFF_X1   (OFF_X0 + TILE_M * XSTRIDE * 4)   // 37888
#define OFF_W    (OFF_X1 + TILE_M * XSTRIDE * 4)   // 72704
#define SMEM_TOTAL (OFF_W + 2 * SLAB_U4 * 16)      // 105472 B -> 2 CTAs/SM

// ---------------- device scratch ----------------
__device__ unsigned g_counts[NE];
__device__ unsigned g_list[NE * NTOK];             // per-expert arenas
// fragment-packed fp16 weights: [l][e][ch(8)][j(4)][ks(8)][lane(32)] uint4
__device__ uint4 g_Wp[NLAYERS * NE * 8 * NMAT * 8 * 32];

// ---------------- helpers ----------------
__device__ __forceinline__ float ex2a(float x) {
    float r; asm("ex2.approx.f32 %0, %1;" : "=f"(r) : "f"(x)); return r;
}
__device__ __forceinline__ float rcpa(float x) {
    float r; asm("rcp.approx.f32 %0, %1;" : "=f"(r) : "f"(x)); return r;
}
__device__ __forceinline__ float sigm(float v) {
    return rcpa(1.0f + ex2a(-1.4426950408889634f * v));
}
__device__ __forceinline__ float tanha(float v) {
    float r; asm("tanh.approx.f32 %0, %1;" : "=f"(r) : "f"(v)); return r;
}
__device__ __forceinline__ uint32_t pkh2(float lo, float hi) {
    __half2 h = __floats2half2_rn(lo, hi);
    return *reinterpret_cast<uint32_t*>(&h);
}
__device__ __forceinline__ float2 uph2(uint32_t u) {
    __half2 h = *reinterpret_cast<__half2*>(&u);
    return __half22float2(h);
}
__device__ __forceinline__ void mma16(float* d, const uint32_t* a, uint32_t b0, uint32_t b1) {
    asm volatile(
        "mma.sync.aligned.m16n8k16.row.col.f32.f16.f16.f32 "
        "{%0,%1,%2,%3}, {%4,%5,%6,%7}, {%8,%9}, {%0,%1,%2,%3};"
        : "+f"(d[0]), "+f"(d[1]), "+f"(d[2]), "+f"(d[3])
        : "r"(a[0]), "r"(a[1]), "r"(a[2]), "r"(a[3]), "r"(b0), "r"(b1));
}
__device__ __forceinline__ void cpa16(uint32_t dst, const void* src) {
    asm volatile("cp.async.cg.shared.global [%0], [%1], 16;"
                 :: "r"(dst), "l"(__cvta_generic_to_global(src)) : "memory");
}

// ---------------- prep kernels (2 launches) ----------------
// pack W[l,j,e][k][n] -> fp16 fragment order per 16-col chunk; also zero counters
__global__ void prep_pack(const float* __restrict__ W) {
    if (blockIdx.x == 0 && threadIdx.x < NE) g_counts[threadIdx.x] = 0;
    int i = blockIdx.x * blockDim.x + threadIdx.x;   // 147456 threads
    int lane = i & 31;
    int ks   = (i >> 5) & 7;
    int j    = (i >> 8) & 3;
    int ch   = (i >> 10) & 7;
    int i2   = i >> 13;
    int e    = i2 % NE;
    int l    = i2 / NE;
    int lk = lane & 3, ln = lane >> 2;
    const float* src = W + ((size_t)(l * NMAT + j) * NE + e) * (D * D);
    int k0 = ks * 16 + lk * 2;
    int colA = ch * 16 + ln;
    int colB = colA + 8;
    uint4 v;
    v.x = pkh2(src[(k0    ) * D + colA], src[(k0 + 1) * D + colA]);
    v.y = pkh2(src[(k0 + 8) * D + colA], src[(k0 + 9) * D + colA]);
    v.z = pkh2(src[(k0    ) * D + colB], src[(k0 + 1) * D + colB]);
    v.w = pkh2(src[(k0 + 8) * D + colB], src[(k0 + 9) * D + colB]);
    g_Wp[i] = v;
}
// scatter tokens into per-expert arenas (order within expert irrelevant)
__global__ void prep_scatter(const int* __restrict__ pos) {
    __shared__ unsigned sc[NE];
    __shared__ unsigned sb[NE];
    if (threadIdx.x < NE) sc[threadIdx.x] = 0;
    __syncthreads();
    int t = blockIdx.x * blockDim.x + threadIdx.x;
    int e = min(pos[t], NE - 1);
    unsigned my = atomicAdd(&sc[e], 1u);
    __syncthreads();
    if (threadIdx.x < NE) sb[threadIdx.x] = atomicAdd(&g_counts[threadIdx.x], sc[threadIdx.x]);
    __syncthreads();
    g_list[(size_t)e * NTOK + sb[e] + my] = (unsigned)t;
}

// ---------------- main kernel ----------------
__global__ __launch_bounds__(NTHR, 2) void mpt_main(
    const float* __restrict__ X0,
    const float* __restrict__ Bv,
    float* __restrict__ Out)
{
    extern __shared__ __align__(16) char sm[];
    unsigned* s_tok = (unsigned*)(sm + OFF_TOK);
    int* s_meta = (int*)(sm + OFF_TOK + 512);
    float* Bs = (float*)(sm + OFF_BIAS);
    const uint32_t smW = (uint32_t)__cvta_generic_to_shared(sm + OFF_W);
    const int tid = threadIdx.x;

    // map block -> (expert, chunk-within-expert, valid rows)
    if (tid == 0) {
        int b = blockIdx.x, acc = 0, ex = -1, loc = 0, vc = 0;
        #pragma unroll
        for (int e2 = 0; e2 < NE; e2++) {
            int cnt = (int)g_counts[e2];
            int pe = (cnt + TILE_M - 1) >> 7;
            if (b < acc + pe) { ex = e2; loc = b - acc; vc = min(TILE_M, cnt - loc * TILE_M); break; }
            acc += pe;
        }
        s_meta[0] = ex; s_meta[1] = vc; s_meta[2] = loc;
    }
    __syncthreads();
    const int e = s_meta[0];
    if (e < 0) return;
    const int vcnt = s_meta[1], loc = s_meta[2];

    if (tid < TILE_M) {
        int idx = (tid < vcnt) ? tid : 0;
        s_tok[tid] = g_list[(size_t)e * NTOK + loc * TILE_M + idx];
    }
    __syncthreads();

    // prologue: prefetch (l=0, ch=0) slab into buffer 0
    {
        const uint4* src = g_Wp + (size_t)e * 8 * SLAB_U4;
        #pragma unroll
        for (int i = 0; i < 8; i++) {
            int idx = tid + i * NTHR;
            cpa16(smW + idx * 16, src + idx);
        }
        asm volatile("cp.async.commit_group;" ::: "memory");
    }

    // gather X tile -> fp16 SMEM (buffer 0)
    {
        uint32_t* Xg = (uint32_t*)(sm + OFF_X0);
        for (int i = tid; i < TILE_M * 32; i += NTHR) {
            int r = i >> 5, c = i & 31;
            unsigned t = s_tok[r];
            float4 v = reinterpret_cast<const float4*>(X0 + (size_t)t * D)[c];
            *reinterpret_cast<uint2*>(Xg + r * XSTRIDE + c * 2) =
                make_uint2(pkh2(v.x, v.y), pkh2(v.z, v.w));
        }
    }

    const int lane = tid & 31, w = tid >> 5;
    const int lk = lane & 3, ln = lane >> 2;
    const int row0 = w * 32 + ln;

    uint32_t* Xs = (uint32_t*)(sm + OFF_X0);
    uint32_t* Xn = (uint32_t*)(sm + OFF_X1);
    int buf = 0;

    #pragma unroll 1
    for (int l = 0; l < NLAYERS; l++) {
        __syncthreads();   // prev layer gating done (Bs reads, Xn writes)
        for (int i = tid; i < NMAT * D; i += NTHR)
            Bs[i] = Bv[((size_t)(l * NMAT + (i >> 7)) * NE + e) * D + (i & 127)];

        #pragma unroll
        for (int ch = 0; ch < 8; ch++) {
            asm volatile("cp.async.wait_group 0;" ::: "memory");
            __syncthreads();   // slab ready; all warps past previous chunk
            int g = l * 8 + ch;
            if (g < 15) {
                int nl = (g + 1) >> 3, nch = (g + 1) & 7;
                const uint4* src = g_Wp + ((size_t)(nl * NE + e) * 8 + nch) * SLAB_U4;
                uint32_t dbase = smW + (buf ^ 1) * (SLAB_U4 * 16);
                #pragma unroll
                for (int i = 0; i < 8; i++) {
                    int idx = tid + i * NTHR;
                    cpa16(dbase + idx * 16, src + idx);
                }
                asm volatile("cp.async.commit_group;" ::: "memory");
            }

            // ---- GEMM: 32 rows/warp x 16 cols x 128 k, 4 matrices ----
            float acc[4][2][2][4];
            #pragma unroll
            for (int m = 0; m < 4; m++)
                #pragma unroll
                for (int rt = 0; rt < 2; rt++)
                    #pragma unroll
                    for (int nt = 0; nt < 2; nt++)
                        #pragma unroll
                        for (int c = 0; c < 4; c++) acc[m][rt][nt][c] = 0.0f;

            const uint32_t* xa = Xs + row0 * XSTRIDE + lk;
            const uint4* wb = (const uint4*)(sm + OFF_W) + buf * SLAB_U4 + lane;

            #pragma unroll
            for (int ks = 0; ks < 8; ks++) {
                uint32_t a0[4], a1[4];
                a0[0] = xa[ks * 8];
                a0[1] = xa[ks * 8 + 8 * XSTRIDE];
                a0[2] = xa[ks * 8 + 4];
                a0[3] = xa[ks * 8 + 8 * XSTRIDE + 4];
                a1[0] = xa[ks * 8 + 16 * XSTRIDE];
                a1[1] = xa[ks * 8 + 24 * XSTRIDE];
                a1[2] = xa[ks * 8 + 16 * XSTRIDE + 4];
                a1[3] = xa[ks * 8 + 24 * XSTRIDE + 4];
                #pragma unroll
                for (int m = 0; m < 4; m++) {
                    uint4 bq = wb[(m * 8 + ks) * 32];
                    mma16(acc[m][0][0], a0, bq.x, bq.y);
                    mma16(acc[m][0][1], a0, bq.z, bq.w);
                    mma16(acc[m][1][0], a1, bq.x, bq.y);
                    mma16(acc[m][1][1], a1, bq.z, bq.w);
                }
            }

            // ---- gating: write straight into new-X buffer ----
            int colbase = ch * 16;
            float2 bv[4][2];
            #pragma unroll
            for (int m = 0; m < 4; m++)
                #pragma unroll
                for (int nt = 0; nt < 2; nt++)
                    bv[m][nt] = *reinterpret_cast<const float2*>(
                        Bs + m * D + colbase + nt * 8 + lk * 2);

            #pragma unroll
            for (int rt = 0; rt < 2; rt++) {
                #pragma unroll
                for (int h = 0; h < 2; h++) {
                    int row = row0 + rt * 16 + h * 8;
                    #pragma unroll
                    for (int nt = 0; nt < 2; nt++) {
                        uint32_t xidx = row * XSTRIDE + ch * 8 + nt * 4 + lk;
                        float2 xv = uph2(Xs[xidx]);
                        float v[2];
                        #pragma unroll
                        for (int c = 0; c < 2; c++) {
                            float sf = acc[0][rt][nt][h * 2 + c] + (&bv[0][nt].x)[c];
                            float lg = acc[1][rt][nt][h * 2 + c] + (&bv[1][nt].x)[c];
                            float lf = acc[2][rt][nt][h * 2 + c] + (&bv[2][nt].x)[c];
                            float of = acc[3][rt][nt][h * 2 + c] + (&bv[3][nt].x)[c];
                            float x1 = (c == 0) ? xv.x : xv.y;
                            float nr = x1 * sigm(sf) + tanha(lg) * sigm(lf);
                            v[c] = tanha(nr) * sigm(of);
                        }
                        Xn[xidx] = pkh2(v[0], v[1]);
                    }
                }
            }
            buf ^= 1;
        }
        // swap X buffers
        uint32_t* tmp = Xs; Xs = Xn; Xn = tmp;
    }

    __syncthreads();
    // coalesced store of final X (fp16 -> fp32), valid rows only
    for (int i = tid; i < TILE_M * 32; i += NTHR) {
        int r = i >> 5, c = i & 31;
        if (r < vcnt) {
            unsigned t = s_tok[r];
            uint2 p = *reinterpret_cast<const uint2*>(Xs + r * XSTRIDE + c * 2);
            float2 lo = uph2(p.x), hi = uph2(p.y);
            reinterpret_cast<float4*>(Out + (size_t)t * D)[c] =
                make_float4(lo.x, lo.y, hi.x, hi.y);
        }
    }
}

// ---------------- launch ----------------
extern "C" void kernel_launch(void* const* d_in, const int* in_sizes, int n_in,
                              void* d_out, int out_size)
{
    const int*   pos = (const int*)d_in[0];
    const float* X0  = (const float*)d_in[1];
    const float* W   = (const float*)d_in[2];
    const float* Bv  = (const float*)d_in[3];
    float*       Out = (float*)d_out;
    (void)in_sizes; (void)n_in; (void)out_size;

    cudaFuncSetAttribute(mpt_main, cudaFuncAttributeMaxDynamicSharedMemorySize, SMEM_TOTAL);

    prep_pack<<<(NLAYERS * NE * 8 * NMAT * 8 * 32) / 256, 256>>>(W);
    prep_scatter<<<NTOK / 256, 256>>>(pos);
    mpt_main<<<NBLK, NTHR, SMEM_TOTAL>>>(X0, Bv, Out);
}

// round 10
// speedup vs baseline: 4.5920x; 1.1673x over previous
#include <cuda_runtime.h>
#include <cuda_fp16.h>
#include <cstdint>

#define NLAYERS 2
#define NMAT 4
#define NE 9
#define D 128
#define NTOK 65536
#define TILE_M 128
#define NBLK (NTOK / TILE_M + NE)     // 521
#define NTHR 128

#define XSTRIDE 68                     // uint32 (half2) per X row
#define SLAB_U4 1024                   // uint4 per 16-col chunk slab (16 KB)

#define OFF_TOK  0
#define OFF_BIAS 1024
#define OFF_X0   3072
#define OFF_X1   (OFF_X0 + TILE_M * XSTRIDE * 4)   // 37888
#define OFF_W    (OFF_X1 + TILE_M * XSTRIDE * 4)   // 72704
#define SMEM_TOTAL (OFF_W + 2 * SLAB_U4 * 16)      // 105472 B -> 2 CTAs/SM

// ---------------- device scratch ----------------
__device__ unsigned g_counts[NE];
__device__ unsigned g_list[NE * NTOK];             // per-expert arenas
// fragment-packed fp16 weights: [l][e][ch(8)][j(4)][ks(8)][lane(32)] uint4
__device__ uint4 g_Wp[NLAYERS * NE * 8 * NMAT * 8 * 32];

// ---------------- helpers ----------------
__device__ __forceinline__ float tanha(float v) {
    float r; asm("tanh.approx.f32 %0, %1;" : "=f"(r) : "f"(v)); return r;
}
__device__ __forceinline__ float sigm(float v) {
    return fmaf(0.5f, tanha(0.5f * v), 0.5f);
}
__device__ __forceinline__ uint32_t pkh2(float lo, float hi) {
    __half2 h = __floats2half2_rn(lo, hi);
    return *reinterpret_cast<uint32_t*>(&h);
}
__device__ __forceinline__ float2 uph2(uint32_t u) {
    __half2 h = *reinterpret_cast<__half2*>(&u);
    return __half22float2(h);
}
__device__ __forceinline__ void mma16(float* d, const uint32_t* a, uint32_t b0, uint32_t b1) {
    asm volatile(
        "mma.sync.aligned.m16n8k16.row.col.f32.f16.f16.f32 "
        "{%0,%1,%2,%3}, {%4,%5,%6,%7}, {%8,%9}, {%0,%1,%2,%3};"
        : "+f"(d[0]), "+f"(d[1]), "+f"(d[2]), "+f"(d[3])
        : "r"(a[0]), "r"(a[1]), "r"(a[2]), "r"(a[3]), "r"(b0), "r"(b1));
}
__device__ __forceinline__ void cpa16(uint32_t dst, const void* src) {
    asm volatile("cp.async.cg.shared.global [%0], [%1], 16;"
                 :: "r"(dst), "l"(__cvta_generic_to_global(src)) : "memory");
}

// ---------------- prep kernels (2 launches) ----------------
// pack W[l,j,e][k][n] -> fp16 fragment order per 16-col chunk; also zero counters
__global__ void prep_pack(const float* __restrict__ W) {
    if (blockIdx.x == 0 && threadIdx.x < NE) g_counts[threadIdx.x] = 0;
    int i = blockIdx.x * blockDim.x + threadIdx.x;   // 147456 threads
    int lane = i & 31;
    int ks   = (i >> 5) & 7;
    int j    = (i >> 8) & 3;
    int ch   = (i >> 10) & 7;
    int i2   = i >> 13;
    int e    = i2 % NE;
    int l    = i2 / NE;
    int lk = lane & 3, ln = lane >> 2;
    const float* src = W + ((size_t)(l * NMAT + j) * NE + e) * (D * D);
    int k0 = ks * 16 + lk * 2;
    int colA = ch * 16 + ln;
    int colB = colA + 8;
    uint4 v;
    v.x = pkh2(src[(k0    ) * D + colA], src[(k0 + 1) * D + colA]);
    v.y = pkh2(src[(k0 + 8) * D + colA], src[(k0 + 9) * D + colA]);
    v.z = pkh2(src[(k0    ) * D + colB], src[(k0 + 1) * D + colB]);
    v.w = pkh2(src[(k0 + 8) * D + colB], src[(k0 + 9) * D + colB]);
    g_Wp[i] = v;
}
// scatter tokens into per-expert arenas (order within expert irrelevant)
__global__ void prep_scatter(const int* __restrict__ pos) {
    __shared__ unsigned sc[NE];
    __shared__ unsigned sb[NE];
    if (threadIdx.x < NE) sc[threadIdx.x] = 0;
    __syncthreads();
    int t = blockIdx.x * blockDim.x + threadIdx.x;
    int e = min(pos[t], NE - 1);
    unsigned my = atomicAdd(&sc[e], 1u);
    __syncthreads();
    if (threadIdx.x < NE) sb[threadIdx.x] = atomicAdd(&g_counts[threadIdx.x], sc[threadIdx.x]);
    __syncthreads();
    g_list[(size_t)e * NTOK + sb[e] + my] = (unsigned)t;
}

// ---------------- main kernel ----------------
__global__ __launch_bounds__(NTHR, 2) void mpt_main(
    const float* __restrict__ X0,
    const float* __restrict__ Bv,
    float* __restrict__ Out)
{
    extern __shared__ __align__(16) char sm[];
    unsigned* s_tok = (unsigned*)(sm + OFF_TOK);
    int* s_meta = (int*)(sm + OFF_TOK + 512);
    float* Bs = (float*)(sm + OFF_BIAS);
    const uint32_t smW = (uint32_t)__cvta_generic_to_shared(sm + OFF_W);
    const int tid = threadIdx.x;

    // map block -> (expert, chunk-within-expert, valid rows)
    if (tid == 0) {
        int b = blockIdx.x, acc = 0, ex = -1, lo = 0, vc = 0;
        #pragma unroll
        for (int e2 = 0; e2 < NE; e2++) {
            int cnt = (int)g_counts[e2];
            int pe = (cnt + TILE_M - 1) >> 7;
            if (b < acc + pe) { ex = e2; lo = b - acc; vc = min(TILE_M, cnt - lo * TILE_M); break; }
            acc += pe;
        }
        s_meta[0] = ex; s_meta[1] = vc; s_meta[2] = lo;
    }
    __syncthreads();
    const int e = s_meta[0];
    if (e < 0) return;
    const int vcnt = s_meta[1], loc = s_meta[2];

    if (tid < TILE_M) {
        int idx = (tid < vcnt) ? tid : 0;
        s_tok[tid] = g_list[(size_t)e * NTOK + loc * TILE_M + idx];
    }
    __syncthreads();

    // prologue: prefetch (l=0, ch=0) slab into buffer 0
    {
        const uint4* src = g_Wp + (size_t)e * 8 * SLAB_U4;
        #pragma unroll
        for (int i = 0; i < 8; i++) {
            int idx = tid + i * NTHR;
            cpa16(smW + idx * 16, src + idx);
        }
        asm volatile("cp.async.commit_group;" ::: "memory");
    }

    // gather X tile -> fp16 SMEM (buffer 0)
    {
        uint32_t* Xg = (uint32_t*)(sm + OFF_X0);
        for (int i = tid; i < TILE_M * 32; i += NTHR) {
            int r = i >> 5, c = i & 31;
            unsigned t = s_tok[r];
            float4 v = reinterpret_cast<const float4*>(X0 + (size_t)t * D)[c];
            *reinterpret_cast<uint2*>(Xg + r * XSTRIDE + c * 2) =
                make_uint2(pkh2(v.x, v.y), pkh2(v.z, v.w));
        }
    }

    const int lane = tid & 31, w = tid >> 5;
    const int lk = lane & 3, ln = lane >> 2;
    const int row0 = w * 32 + ln;

    uint32_t* Xs = (uint32_t*)(sm + OFF_X0);
    uint32_t* Xn = (uint32_t*)(sm + OFF_X1);
    int buf = 0;

    #pragma unroll 1
    for (int l = 0; l < NLAYERS; l++) {
        __syncthreads();   // prev layer gating done (Bs reads, Xn writes)
        for (int i = tid; i < NMAT * D; i += NTHR)
            Bs[i] = Bv[((size_t)(l * NMAT + (i >> 7)) * NE + e) * D + (i & 127)];

        #pragma unroll
        for (int ch = 0; ch < 8; ch++) {
            asm volatile("cp.async.wait_group 0;" ::: "memory");
            __syncthreads();   // slab ready; all warps past previous chunk
            int g = l * 8 + ch;
            if (g < 15) {
                int nl = (g + 1) >> 3, nch = (g + 1) & 7;
                const uint4* src = g_Wp + ((size_t)(nl * NE + e) * 8 + nch) * SLAB_U4;
                uint32_t dbase = smW + (buf ^ 1) * (SLAB_U4 * 16);
                #pragma unroll
                for (int i = 0; i < 8; i++) {
                    int idx = tid + i * NTHR;
                    cpa16(dbase + idx * 16, src + idx);
                }
                asm volatile("cp.async.commit_group;" ::: "memory");
            }

            // ---- GEMM: 32 rows/warp x 16 cols x 128 k, 4 matrices ----
            float acc[4][2][2][4];
            #pragma unroll
            for (int m = 0; m < 4; m++)
                #pragma unroll
                for (int rt = 0; rt < 2; rt++)
                    #pragma unroll
                    for (int nt = 0; nt < 2; nt++)
                        #pragma unroll
                        for (int c = 0; c < 4; c++) acc[m][rt][nt][c] = 0.0f;

            const uint32_t* xa = Xs + row0 * XSTRIDE + lk;
            const uint4* wb = (const uint4*)(sm + OFF_W) + buf * SLAB_U4 + lane;

            #pragma unroll
            for (int ks = 0; ks < 8; ks++) {
                uint32_t a0[4], a1[4];
                a0[0] = xa[ks * 8];
                a0[1] = xa[ks * 8 + 8 * XSTRIDE];
                a0[2] = xa[ks * 8 + 4];
                a0[3] = xa[ks * 8 + 8 * XSTRIDE + 4];
                a1[0] = xa[ks * 8 + 16 * XSTRIDE];
                a1[1] = xa[ks * 8 + 24 * XSTRIDE];
                a1[2] = xa[ks * 8 + 16 * XSTRIDE + 4];
                a1[3] = xa[ks * 8 + 24 * XSTRIDE + 4];
                #pragma unroll
                for (int m = 0; m < 4; m++) {
                    uint4 bq = wb[(m * 8 + ks) * 32];
                    mma16(acc[m][0][0], a0, bq.x, bq.y);
                    mma16(acc[m][0][1], a0, bq.z, bq.w);
                    mma16(acc[m][1][0], a1, bq.x, bq.y);
                    mma16(acc[m][1][1], a1, bq.z, bq.w);
                }
            }

            // ---- gating: layer 0 -> new-X smem; layer 1 -> fp32 gmem ----
            int colbase = ch * 16;
            float2 bv[4][2];
            #pragma unroll
            for (int m = 0; m < 4; m++)
                #pragma unroll
                for (int nt = 0; nt < 2; nt++)
                    bv[m][nt] = *reinterpret_cast<const float2*>(
                        Bs + m * D + colbase + nt * 8 + lk * 2);

            #pragma unroll
            for (int rt = 0; rt < 2; rt++) {
                #pragma unroll
                for (int h = 0; h < 2; h++) {
                    int row = row0 + rt * 16 + h * 8;
                    #pragma unroll
                    for (int nt = 0; nt < 2; nt++) {
                        uint32_t xidx = row * XSTRIDE + ch * 8 + nt * 4 + lk;
                        float2 xv = uph2(Xs[xidx]);
                        float v[2];
                        #pragma unroll
                        for (int c = 0; c < 2; c++) {
                            float sf = acc[0][rt][nt][h * 2 + c] + (&bv[0][nt].x)[c];
                            float lg = acc[1][rt][nt][h * 2 + c] + (&bv[1][nt].x)[c];
                            float lf = acc[2][rt][nt][h * 2 + c] + (&bv[2][nt].x)[c];
                            float of = acc[3][rt][nt][h * 2 + c] + (&bv[3][nt].x)[c];
                            float x1 = (c == 0) ? xv.x : xv.y;
                            float nr = x1 * sigm(sf) + tanha(lg) * sigm(lf);
                            v[c] = tanha(nr) * sigm(of);
                        }
                        if (l == 0) {
                            Xn[xidx] = pkh2(v[0], v[1]);
                        } else if (row < vcnt) {
                            unsigned t = s_tok[row];
                            *reinterpret_cast<float2*>(Out + (size_t)t * D
                                + colbase + nt * 8 + lk * 2) = make_float2(v[0], v[1]);
                        }
                    }
                }
            }
            buf ^= 1;
        }
        // swap X buffers
        uint32_t* tmp = Xs; Xs = Xn; Xn = tmp;
    }
}

// ---------------- launch ----------------
extern "C" void kernel_launch(void* const* d_in, const int* in_sizes, int n_in,
                              void* d_out, int out_size)
{
    const int*   pos = (const int*)d_in[0];
    const float* X0  = (const float*)d_in[1];
    const float* W   = (const float*)d_in[2];
    const float* Bv  = (const float*)d_in[3];
    float*       Out = (float*)d_out;
    (void)in_sizes; (void)n_in; (void)out_size;

    cudaFuncSetAttribute(mpt_main, cudaFuncAttributeMaxDynamicSharedMemorySize, SMEM_TOTAL);

    prep_pack<<<(NLAYERS * NE * 8 * NMAT * 8 * 32) / 256, 256>>>(W);
    prep_scatter<<<NTOK / 256, 256>>>(pos);
    mpt_main<<<NBLK, NTHR, SMEM_TOTAL>>>(X0, Bv, Out);
}

// round 11
// speedup vs baseline: 5.0943x; 1.1094x over previous
#include <cuda_runtime.h>
#include <cuda_fp16.h>
#include <cstdint>

#define NLAYERS 2
#define NMAT 4
#define NE 9
#define D 128
#define NTOK 65536
#define TILE_M 128
#define NBLK (NTOK / TILE_M + NE)     // 521
#define NTHR 128

#define SLAB_U4 1024                   // uint4 per 16-col chunk slab (16 KB)
#define OFF_BIAS 0                     // 2 layers x 4 mats x 128 floats = 4 KB
#define OFF_W    4096
#define SMEM_TOTAL (OFF_W + 2 * SLAB_U4 * 16)   // 36864 B -> 2 CTAs/SM easily

// ---------------- device scratch ----------------
__device__ unsigned g_counts[NE];
__device__ unsigned g_list[NE * NTOK];             // per-expert arenas
// fragment-packed fp16 weights: [l][e][ch(8)][j(4)][ks(8)][lane(32)] uint4
__device__ uint4 g_Wp[NLAYERS * NE * 8 * NMAT * 8 * 32];

// ---------------- helpers ----------------
__device__ __forceinline__ float tanha(float v) {
    float r; asm("tanh.approx.f32 %0, %1;" : "=f"(r) : "f"(v)); return r;
}
__device__ __forceinline__ float sigm(float v) {
    return fmaf(0.5f, tanha(0.5f * v), 0.5f);
}
__device__ __forceinline__ uint32_t pkh2(float lo, float hi) {
    __half2 h = __floats2half2_rn(lo, hi);
    return *reinterpret_cast<uint32_t*>(&h);
}
__device__ __forceinline__ float2 uph2(uint32_t u) {
    __half2 h = *reinterpret_cast<__half2*>(&u);
    return __half22float2(h);
}
__device__ __forceinline__ void mma16(float* d, const uint32_t* a, uint32_t b0, uint32_t b1) {
    asm volatile(
        "mma.sync.aligned.m16n8k16.row.col.f32.f16.f16.f32 "
        "{%0,%1,%2,%3}, {%4,%5,%6,%7}, {%8,%9}, {%0,%1,%2,%3};"
        : "+f"(d[0]), "+f"(d[1]), "+f"(d[2]), "+f"(d[3])
        : "r"(a[0]), "r"(a[1]), "r"(a[2]), "r"(a[3]), "r"(b0), "r"(b1));
}
__device__ __forceinline__ void cpa16(uint32_t dst, const void* src) {
    asm volatile("cp.async.cg.shared.global [%0], [%1], 16;"
                 :: "r"(dst), "l"(__cvta_generic_to_global(src)) : "memory");
}

// ---------------- prep kernels (2 launches) ----------------
__global__ void prep_pack(const float* __restrict__ W) {
    if (blockIdx.x == 0 && threadIdx.x < NE) g_counts[threadIdx.x] = 0;
    int i = blockIdx.x * blockDim.x + threadIdx.x;   // 147456 threads
    int lane = i & 31;
    int ks   = (i >> 5) & 7;
    int j    = (i >> 8) & 3;
    int ch   = (i >> 10) & 7;
    int i2   = i >> 13;
    int e    = i2 % NE;
    int l    = i2 / NE;
    int lk = lane & 3, ln = lane >> 2;
    const float* src = W + ((size_t)(l * NMAT + j) * NE + e) * (D * D);
    int k0 = ks * 16 + lk * 2;
    int colA = ch * 16 + ln;
    int colB = colA + 8;
    uint4 v;
    v.x = pkh2(src[(k0    ) * D + colA], src[(k0 + 1) * D + colA]);
    v.y = pkh2(src[(k0 + 8) * D + colA], src[(k0 + 9) * D + colA]);
    v.z = pkh2(src[(k0    ) * D + colB], src[(k0 + 1) * D + colB]);
    v.w = pkh2(src[(k0 + 8) * D + colB], src[(k0 + 9) * D + colB]);
    g_Wp[i] = v;
}
__global__ void prep_scatter(const int* __restrict__ pos) {
    __shared__ unsigned sc[NE];
    __shared__ unsigned sb[NE];
    if (threadIdx.x < NE) sc[threadIdx.x] = 0;
    __syncthreads();
    int t = blockIdx.x * blockDim.x + threadIdx.x;
    int e = min(pos[t], NE - 1);
    unsigned my = atomicAdd(&sc[e], 1u);
    __syncthreads();
    if (threadIdx.x < NE) sb[threadIdx.x] = atomicAdd(&g_counts[threadIdx.x], sc[threadIdx.x]);
    __syncthreads();
    g_list[(size_t)e * NTOK + sb[e] + my] = (unsigned)t;
}

// ---------------- per-layer body (inlined; register arrays stay static) ----------------
template<int L>
__device__ __forceinline__ void do_layer(
    uint32_t (&xin)[4][8][2], uint32_t (&xout)[4][8][2],
    char* sm, uint32_t smW, int& buf, int e,
    int lane, int lk, int row0, const unsigned* tokr, int vcnt,
    float* __restrict__ Out, int tid)
{
    const float* Bs = (const float*)(sm + OFF_BIAS) + L * NMAT * D;

    #pragma unroll
    for (int ch = 0; ch < 8; ch++) {
        asm volatile("cp.async.wait_group 0;" ::: "memory");
        __syncthreads();   // slab[buf] ready; all warps done with slab[buf^1]
        int g = L * 8 + ch;
        if (g < 15) {
            int nl = (g + 1) >> 3, nch = (g + 1) & 7;
            const uint4* src = g_Wp + ((size_t)(nl * NE + e) * 8 + nch) * SLAB_U4;
            uint32_t dbase = smW + (buf ^ 1) * (SLAB_U4 * 16);
            #pragma unroll
            for (int i = 0; i < 8; i++) {
                int idx = tid + i * NTHR;
                cpa16(dbase + idx * 16, src + idx);
            }
            asm volatile("cp.async.commit_group;" ::: "memory");
        }

        // ---- GEMM: 32 rows/warp x 16 cols x 128 k, 4 matrices; A from registers ----
        float acc[4][2][2][4];
        #pragma unroll
        for (int m = 0; m < 4; m++)
            #pragma unroll
            for (int rt = 0; rt < 2; rt++)
                #pragma unroll
                for (int nt = 0; nt < 2; nt++)
                    #pragma unroll
                    for (int c = 0; c < 4; c++) acc[m][rt][nt][c] = 0.0f;

        const uint4* wb = (const uint4*)(sm + OFF_W) + buf * SLAB_U4 + lane;

        #pragma unroll
        for (int ks = 0; ks < 8; ks++) {
            uint32_t a0[4] = { xin[0][ks][0], xin[1][ks][0], xin[0][ks][1], xin[1][ks][1] };
            uint32_t a1[4] = { xin[2][ks][0], xin[3][ks][0], xin[2][ks][1], xin[3][ks][1] };
            #pragma unroll
            for (int m = 0; m < 4; m++) {
                uint4 bq = wb[(m * 8 + ks) * 32];
                mma16(acc[m][0][0], a0, bq.x, bq.y);
                mma16(acc[m][0][1], a0, bq.z, bq.w);
                mma16(acc[m][1][0], a1, bq.x, bq.y);
                mma16(acc[m][1][1], a1, bq.z, bq.w);
            }
        }

        // ---- gating ----
        float2 bv[4][2];
        #pragma unroll
        for (int m = 0; m < 4; m++)
            #pragma unroll
            for (int nt = 0; nt < 2; nt++)
                bv[m][nt] = *reinterpret_cast<const float2*>(
                    Bs + m * D + ch * 16 + nt * 8 + lk * 2);

        #pragma unroll
        for (int rt = 0; rt < 2; rt++) {
            #pragma unroll
            for (int h = 0; h < 2; h++) {
                int ri = rt * 2 + h;
                #pragma unroll
                for (int nt = 0; nt < 2; nt++) {
                    float2 xv = uph2(xin[ri][ch][nt]);
                    float v[2];
                    #pragma unroll
                    for (int c = 0; c < 2; c++) {
                        float sf = acc[0][rt][nt][h * 2 + c] + (&bv[0][nt].x)[c];
                        float lg = acc[1][rt][nt][h * 2 + c] + (&bv[1][nt].x)[c];
                        float lf = acc[2][rt][nt][h * 2 + c] + (&bv[2][nt].x)[c];
                        float of = acc[3][rt][nt][h * 2 + c] + (&bv[3][nt].x)[c];
                        float x1 = (c == 0) ? xv.x : xv.y;
                        float nr = x1 * sigm(sf) + tanha(lg) * sigm(lf);
                        v[c] = tanha(nr) * sigm(of);
                    }
                    if (L == 0) {
                        xout[ri][ch][nt] = pkh2(v[0], v[1]);
                    } else {
                        int row = row0 + ri * 8;
                        if (row < vcnt) {
                            *reinterpret_cast<float2*>(Out + (size_t)tokr[ri] * D
                                + ch * 16 + nt * 8 + lk * 2) = make_float2(v[0], v[1]);
                        }
                    }
                }
            }
        }
        buf ^= 1;
    }
}

// ---------------- main kernel ----------------
__global__ __launch_bounds__(NTHR, 2) void mpt_main(
    const float* __restrict__ X0,
    const float* __restrict__ Bv,
    float* __restrict__ Out)
{
    extern __shared__ __align__(16) char sm[];
    const uint32_t smW = (uint32_t)__cvta_generic_to_shared(sm + OFF_W);
    const int tid = threadIdx.x;

    // every thread computes block -> (expert, chunk, valid) itself (no smem, no barrier)
    int e = -1, loc = 0, vcnt = 0;
    {
        int b = blockIdx.x, acc = 0;
        #pragma unroll
        for (int e2 = 0; e2 < NE; e2++) {
            int cnt = (int)g_counts[e2];
            int pe = (cnt + TILE_M - 1) >> 7;
            if (e < 0 && b < acc + pe) {
                e = e2; loc = b - acc; vcnt = min(TILE_M, cnt - loc * TILE_M);
            }
            acc += pe;
        }
    }
    if (e < 0) return;

    // prefetch (l=0, ch=0) slab into buffer 0
    {
        const uint4* src = g_Wp + (size_t)e * 8 * SLAB_U4;
        #pragma unroll
        for (int i = 0; i < 8; i++) {
            int idx = tid + i * NTHR;
            cpa16(smW + idx * 16, src + idx);
        }
        asm volatile("cp.async.commit_group;" ::: "memory");
    }

    // biases for both layers
    for (int i = tid; i < NLAYERS * NMAT * D; i += NTHR) {
        int l = i >> 9, j = (i >> 7) & 3, f = i & 127;
        ((float*)(sm + OFF_BIAS))[i] = Bv[((size_t)(l * NMAT + j) * NE + e) * D + f];
    }

    const int lane = tid & 31, w = tid >> 5;
    const int lk = lane & 3, ln = lane >> 2;
    const int row0 = w * 32 + ln;

    // this thread's 4 tokens (+padding rule) and X fragments in registers
    unsigned tokr[4];
    #pragma unroll
    for (int ri = 0; ri < 4; ri++) {
        int r = row0 + ri * 8;
        tokr[ri] = g_list[(size_t)e * NTOK + loc * TILE_M + ((r < vcnt) ? r : 0)];
    }

    uint32_t xf[4][8][2], xn[4][8][2];
    #pragma unroll
    for (int ri = 0; ri < 4; ri++) {
        const float* xrow = X0 + (size_t)tokr[ri] * D + lk * 2;
        #pragma unroll
        for (int ks = 0; ks < 8; ks++) {
            #pragma unroll
            for (int s = 0; s < 2; s++) {
                float2 v = *reinterpret_cast<const float2*>(xrow + ks * 16 + s * 8);
                xf[ri][ks][s] = pkh2(v.x, v.y);
            }
        }
    }

    int buf = 0;
    do_layer<0>(xf, xn, sm, smW, buf, e, lane, lk, row0, tokr, vcnt, Out, tid);
    do_layer<1>(xn, xf, sm, smW, buf, e, lane, lk, row0, tokr, vcnt, Out, tid);
}

// ---------------- launch ----------------
extern "C" void kernel_launch(void* const* d_in, const int* in_sizes, int n_in,
                              void* d_out, int out_size)
{
    const int*   pos = (const int*)d_in[0];
    const float* X0  = (const float*)d_in[1];
    const float* W   = (const float*)d_in[2];
    const float* Bv  = (const float*)d_in[3];
    float*       Out = (float*)d_out;
    (void)in_sizes; (void)n_in; (void)out_size;

    cudaFuncSetAttribute(mpt_main, cudaFuncAttributeMaxDynamicSharedMemorySize, SMEM_TOTAL);

    prep_pack<<<(NLAYERS * NE * 8 * NMAT * 8 * 32) / 256, 256>>>(W);
    prep_scatter<<<NTOK / 256, 256>>>(pos);
    mpt_main<<<NBLK, NTHR, SMEM_TOTAL>>>(X0, Bv, Out);
}